// round 8
// baseline (speedup 1.0000x reference)
#include <cuda_runtime.h>
#include <math.h>
#include <cstdint>

typedef unsigned long long ull;

// Problem constants
#define L_STEPS 128
#define NB 64
#define HID 4096            // 32*16*8
#define T1S 128             // t1 row stride (words)
#define T2R 160             // t2 row stride; (e,c) -> e*10 + c

// XW scratch: (L, 3, N, 4096) fp32 = 402 MB.
__device__ float g_xw[(size_t)L_STEPS * 3 * NB * HID];

__device__ __forceinline__ void fma2(ull& acc, ull a, ull b) {
    asm("fma.rn.f32x2 %0, %1, %2, %0;" : "+l"(acc) : "l"(a), "l"(b));
}
__device__ __forceinline__ ull dup2(float x) {
    ull r; asm("mov.b64 %0, {%1, %1};" : "=l"(r) : "f"(x)); return r;
}
__device__ __forceinline__ ull pack2(float lo, float hi) {
    ull r; asm("mov.b64 %0, {%1, %2};" : "=l"(r) : "f"(lo), "f"(hi)); return r;
}
__device__ __forceinline__ uint32_t smem_u32(const void* p) {
    uint32_t a;
    asm("{ .reg .u64 t; cvta.to.shared.u64 t, %1; cvt.u32.u64 %0, t; }" : "=r"(a) : "l"(p));
    return a;
}
__device__ __forceinline__ uint32_t mapa_u32(uint32_t addr, uint32_t rank) {
    uint32_t r;
    asm("mapa.shared::cluster.u32 %0, %1, %2;" : "=r"(r) : "r"(addr), "r"(rank));
    return r;
}
__device__ __forceinline__ void st_cluster_b64(uint32_t addr, ull v) {
    asm volatile("st.shared::cluster.b64 [%0], %1;" :: "r"(addr), "l"(v) : "memory");
}

// ---------------------------------------------------------------------------
// Stage 1: XW[l,g,n,:] = x[n,l,:] x1 W1[g] x2 W2[g] x3 W3[g]
// One CTA per (n,l); 1024 threads (32 warps).
// p1: 12 row-groups (8 rows) x 2 col-halves = 24 warps. p2/p3: all 32 warps.
// ---------------------------------------------------------------------------
__global__ __launch_bounds__(1024) void xw_kernel(
    const float* __restrict__ x,
    const float* __restrict__ W1,   // (3,32,32)
    const float* __restrict__ W2,   // (3,16,16)
    const float* __restrict__ W3)   // (3,8,8)
{
    extern __shared__ float sm[];
    float* xs  = sm;              // 4096: x[a][b*8+c]
    float* t1  = xs + 4096;       // 96*T1S = 12288, rows r = g*32+d
    float* t2  = t1 + 12288;      // 96*T2R = 15360
    float* w1t = t2 + 15360;      // 3072: w1t[a*96 + g*32 + d] = W1[g,d,a]
    float* w2t = w1t + 3072;      // 768:  w2t[g*256 + b*16 + e] = W2[g,e,b]
    float* w3s = w2t + 768;       // 192

    const int t = threadIdx.x;
    const int n = blockIdx.x;
    const int l = blockIdx.y;

    {
        const float4* xg4 = reinterpret_cast<const float4*>(x + ((size_t)n * L_STEPS + l) * HID);
        float4* xs4 = reinterpret_cast<float4*>(xs);
        if (t < 1024) xs4[t] = xg4[t];
    }
    for (int i = t; i < 3072; i += 1024) {
        int g = i >> 10, rem = i & 1023, d = rem >> 5, a = rem & 31;
        w1t[a * 96 + g * 32 + d] = W1[i];
    }
    if (t < 768) {
        int g = t >> 8, rem = t & 255, e = rem >> 4, b = rem & 15;
        w2t[g * 256 + b * 16 + e] = W2[t];
    }
    if (t < 192) w3s[t] = W3[t];
    __syncthreads();

    const int warp = t >> 5, lane = t & 31;

    // ---- phase 1: t1[r][bc] = sum_a W1t[a][r] * x[a][bc]  (24 warps) ----
    if (warp < 24) {
        const int r0 = (warp >> 1) * 8;                 // 8-row group
        const int cb = (warp & 1) * 64 + lane * 2;      // column half, 2 cols/lane
        ull acc[8];
#pragma unroll
        for (int j = 0; j < 8; j++) acc[j] = 0;
#pragma unroll
        for (int a = 0; a < 32; a++) {
            ull xv = *reinterpret_cast<const ull*>(&xs[a * 128 + cb]);
            float4 wa = *reinterpret_cast<const float4*>(&w1t[a * 96 + r0]);
            float4 wb = *reinterpret_cast<const float4*>(&w1t[a * 96 + r0 + 4]);
            fma2(acc[0], dup2(wa.x), xv);
            fma2(acc[1], dup2(wa.y), xv);
            fma2(acc[2], dup2(wa.z), xv);
            fma2(acc[3], dup2(wa.w), xv);
            fma2(acc[4], dup2(wb.x), xv);
            fma2(acc[5], dup2(wb.y), xv);
            fma2(acc[6], dup2(wb.z), xv);
            fma2(acc[7], dup2(wb.w), xv);
        }
#pragma unroll
        for (int j = 0; j < 8; j++)
            *reinterpret_cast<ull*>(&t1[(r0 + j) * T1S + cb]) = acc[j];
    }
    __syncthreads();

    // ---- phase 2: t2[r][e*10+c] = sum_b W2[g,e,b] * t1[r][b*8+c]  (32 warps, 3 rows each) ----
    {
        const int e  = lane >> 1;
        const int c4 = (lane & 1) * 4;
#pragma unroll
        for (int j = 0; j < 3; j++) {
            const int r = warp * 3 + j;
            const int g = r >> 5;
            const float* w2g = w2t + g * 256;
            const float* t1r = t1 + r * T1S;
            ull a0 = 0, a1 = 0;
#pragma unroll
            for (int b = 0; b < 16; b++) {
                ulonglong2 tv = *reinterpret_cast<const ulonglong2*>(&t1r[b * 8 + c4]);
                ull wd = dup2(w2g[b * 16 + e]);
                fma2(a0, wd, tv.x);
                fma2(a1, wd, tv.y);
            }
            float* t2r = t2 + r * T2R + e * 10 + c4;
            *reinterpret_cast<ull*>(t2r)     = a0;
            *reinterpret_cast<ull*>(t2r + 2) = a1;
        }
    }
    __syncthreads();

    // ---- phase 3: out[(d*16+e)*8+f] = sum_c W3[g,f,c] * t2[g*32+d][e*10+c] ----
    {
        const int d  = t >> 5;
        const int e  = (t >> 1) & 15;
        const int f0 = (t & 1) * 4;
#pragma unroll
        for (int g = 0; g < 3; g++) {
            const float* t2c = t2 + (g * 32 + d) * T2R + e * 10;
            float col[8];
#pragma unroll
            for (int k = 0; k < 4; k++) {
                float2 v = *reinterpret_cast<const float2*>(&t2c[k * 2]);
                col[2 * k] = v.x;  col[2 * k + 1] = v.y;
            }
            const float* w3g = w3s + g * 64;
            float o[4];
#pragma unroll
            for (int j = 0; j < 4; j++) {
                float4 ua = *reinterpret_cast<const float4*>(&w3g[(f0 + j) * 8]);
                float4 ub = *reinterpret_cast<const float4*>(&w3g[(f0 + j) * 8 + 4]);
                o[j] = ua.x * col[0] + ua.y * col[1] + ua.z * col[2] + ua.w * col[3]
                     + ub.x * col[4] + ub.y * col[5] + ub.z * col[6] + ub.w * col[7];
            }
            float* outg = g_xw + (((size_t)l * 3 + g) * NB + n) * HID + (d * 16 + e) * 8 + f0;
            *reinterpret_cast<float4*>(outg) = make_float4(o[0], o[1], o[2], o[3]);
        }
    }
}

// ---------------------------------------------------------------------------
// Stage 2: GRU recurrence. Cluster of 2 CTAs per sample (128 CTAs, 1024 thr).
// CTA owns d in [rank*16, rank*16+16).
// p1: 12 row-groups (4 rows) x 2 col-halves = 24 warps. p2: 24 warps x 2 rows.
// p3: all 32 warps, 2 elems/thread. DSMEM half-exchange + 1 cluster barrier/step.
// ---------------------------------------------------------------------------
__global__ __launch_bounds__(1024) __cluster_dims__(2, 1, 1)
void gru_kernel(
    const float* __restrict__ U1,   // (3,32,32)
    const float* __restrict__ U2,   // (3,16,16)
    const float* __restrict__ U3,   // (3,8,8)
    float* __restrict__ out)        // outs (N,L,4096) then h_last (N,4096)
{
    extern __shared__ float sm[];
    float* h0  = sm;                 // 4096
    float* h1  = h0 + 4096;          // 4096
    float* t1  = h1 + 4096;          // 48*T1S = 6144   rows r = g*16+dd
    float* t2  = t1 + 6144;          // 48*T2R = 7680
    float* u1t = t2 + 7680;          // 1536: u1t[a*48 + g*16 + dd] = U1[g, rank*16+dd, a]
    float* w2t = u1t + 1536;         // 768:  w2t[g*256 + b*16 + e] = U2[g,e,b]
    float* u3s = w2t + 768;          // 192

    const int t    = threadIdx.x;
    const int n    = blockIdx.x >> 1;
    const int rank = blockIdx.x & 1;
    const int peer = rank ^ 1;

    for (int i = t; i < 4096; i += 1024) h0[i] = 0.f;
    for (int i = t; i < 1536; i += 1024) {
        int g = i >> 9, rem = i & 511, dd = rem >> 5, a = rem & 31;
        u1t[a * 48 + g * 16 + dd] = U1[((g * 32) + rank * 16 + dd) * 32 + a];
    }
    if (t < 768) {
        int g = t >> 8, rem = t & 255, e = rem >> 4, b = rem & 15;
        w2t[g * 256 + b * 16 + e] = U2[t];
    }
    if (t < 192) u3s[t] = U3[t];
    __syncthreads();

    const uint32_t h0a = smem_u32(h0);
    const uint32_t h1a = smem_u32(h1);

    const int warp = t >> 5, lane = t & 31;
    // p1: 12 groups of 4 rows x 2 col-halves
    const int r0 = (warp >> 1) * 4;
    const int cb = (warp & 1) * 64 + lane * 2;
    // p2: warp -> 2 rows; lane -> (e, c-half)
    const int e2 = lane >> 1;
    const int c4 = (lane & 1) * 4;
    // p3: thread -> (dd, e, f-pair)
    const int dd3 = t >> 6;
    const int e3  = (t >> 2) & 15;
    const int f0  = (t & 3) * 2;
    const int gb2 = ((rank * 16 + dd3) * 16 + e3) * 8 + f0;   // 2 global hidden elems

    float* hc = h0;
    float* hn = h1;

    for (int l = 0; l < L_STEPS; l++) {
        // XW prefetch for phase 3 — issued first, hidden under p1/p2
        float2 xf[3];
#pragma unroll
        for (int g = 0; g < 3; g++)
            xf[g] = *reinterpret_cast<const float2*>(
                g_xw + (((size_t)l * 3 + g) * NB + n) * HID + gb2);

        // ---- phase 1 (24 warps): t1[r][bc] = sum_a u1t[a][r]*hc[a*128+bc] ----
        if (warp < 24) {
            ull acc[4];
#pragma unroll
            for (int j = 0; j < 4; j++) acc[j] = 0;
#pragma unroll
            for (int a = 0; a < 32; a++) {
                ull hv = *reinterpret_cast<const ull*>(&hc[a * 128 + cb]);
                float4 wv = *reinterpret_cast<const float4*>(&u1t[a * 48 + r0]);
                fma2(acc[0], dup2(wv.x), hv);
                fma2(acc[1], dup2(wv.y), hv);
                fma2(acc[2], dup2(wv.z), hv);
                fma2(acc[3], dup2(wv.w), hv);
            }
#pragma unroll
            for (int j = 0; j < 4; j++)
                *reinterpret_cast<ull*>(&t1[(r0 + j) * T1S + cb]) = acc[j];
        }
        __syncthreads();

        // ---- phase 2 (24 warps x 2 rows): t2[r][e*10+c] = sum_b U2[g,e,b]*t1[r][b*8+c] ----
        if (warp < 24) {
#pragma unroll
            for (int j = 0; j < 2; j++) {
                const int r = warp * 2 + j;
                const int g = r >> 4;
                const float* w2g = w2t + g * 256;
                const float* t1r = t1 + r * T1S;
                ull a0 = 0, a1 = 0;
#pragma unroll
                for (int b = 0; b < 16; b++) {
                    ulonglong2 tv = *reinterpret_cast<const ulonglong2*>(&t1r[b * 8 + c4]);
                    ull wd = dup2(w2g[b * 16 + e2]);
                    fma2(a0, wd, tv.x);
                    fma2(a1, wd, tv.y);
                }
                float* t2r = t2 + r * T2R + e2 * 10 + c4;
                *reinterpret_cast<ull*>(t2r)     = a0;
                *reinterpret_cast<ull*>(t2r + 2) = a1;
            }
        }
        __syncthreads();

        // ---- phase 3: mode-3 + gate combine for 2 elements (gb2, gb2+1) ----
        float hu[3][2];
#pragma unroll
        for (int g = 0; g < 3; g++) {
            const float* t2c = t2 + (g * 16 + dd3) * T2R + e3 * 10;
            float col[8];
#pragma unroll
            for (int k = 0; k < 4; k++) {
                float2 v = *reinterpret_cast<const float2*>(&t2c[k * 2]);
                col[2 * k] = v.x;  col[2 * k + 1] = v.y;
            }
            const float* u3g = u3s + g * 64;
#pragma unroll
            for (int j = 0; j < 2; j++) {
                float4 ua = *reinterpret_cast<const float4*>(&u3g[(f0 + j) * 8]);
                float4 ub = *reinterpret_cast<const float4*>(&u3g[(f0 + j) * 8 + 4]);
                hu[g][j] = ua.x * col[0] + ua.y * col[1] + ua.z * col[2] + ua.w * col[3]
                         + ub.x * col[4] + ub.y * col[5] + ub.z * col[6] + ub.w * col[7];
            }
        }
        float2 ho = *reinterpret_cast<const float2*>(&hc[gb2]);
        float hold[2] = {ho.x, ho.y};
        float xz[2] = {xf[0].x, xf[0].y};
        float xr[2] = {xf[1].x, xf[1].y};
        float xh[2] = {xf[2].x, xf[2].y};

        float res[2];
#pragma unroll
        for (int j = 0; j < 2; j++) {
            float z  = 1.f / (1.f + __expf(-(xz[j] + hu[0][j])));
            float r  = 1.f / (1.f + __expf(-(xr[j] + hu[1][j])));
            float ax = xh[j] + r * hu[2][j];
            float e2x = __expf(2.f * ax);
            float hh = 1.f - 2.f / (e2x + 1.f);      // tanh, NaN-safe
            res[j] = z * hold[j] + (1.f - z) * hh;
        }
        ull r2 = pack2(res[0], res[1]);
        *reinterpret_cast<ull*>(&hn[gb2]) = r2;

        // publish our half to peer's hn via DSMEM (1x b64)
        {
            uint32_t hna = (l & 1) ? h0a : h1a;
            uint32_t ra = mapa_u32(hna + (uint32_t)gb2 * 4u, (uint32_t)peer);
            st_cluster_b64(ra, r2);
        }

        // split cluster barrier: hide STG + barrier latency
        asm volatile("barrier.cluster.arrive.aligned;" ::: "memory");
        *reinterpret_cast<ull*>(out + ((size_t)n * L_STEPS + l) * HID + gb2) = r2;
        asm volatile("barrier.cluster.wait.aligned;"   ::: "memory");

        float* tmp = hc; hc = hn; hn = tmp;
    }

    // h_last: each CTA writes its own half
    float* hl = out + (size_t)NB * L_STEPS * HID + (size_t)n * HID + rank * 2048;
    const float* hsrc = hc + rank * 2048;
    for (int i = t; i < 2048; i += 1024) hl[i] = hsrc[i];
}

// ---------------------------------------------------------------------------
extern "C" void kernel_launch(void* const* d_in, const int* in_sizes, int n_in,
                              void* d_out, int out_size)
{
    const float* x  = (const float*)d_in[0];
    const float* W1 = (const float*)d_in[1];
    const float* W2 = (const float*)d_in[2];
    const float* W3 = (const float*)d_in[3];
    const float* U1 = (const float*)d_in[4];
    const float* U2 = (const float*)d_in[5];
    const float* U3 = (const float*)d_in[6];
    float* out = (float*)d_out;

    const int SMEM1 = (4096 + 12288 + 15360 + 3072 + 768 + 192) * (int)sizeof(float);
    const int SMEM2 = (4096 * 2 + 6144 + 7680 + 1536 + 768 + 192) * (int)sizeof(float);

    cudaFuncSetAttribute(xw_kernel,  cudaFuncAttributeMaxDynamicSharedMemorySize, SMEM1);
    cudaFuncSetAttribute(gru_kernel, cudaFuncAttributeMaxDynamicSharedMemorySize, SMEM2);

    dim3 grid1(NB, L_STEPS);
    xw_kernel<<<grid1, 1024, SMEM1>>>(x, W1, W2, W3);
    gru_kernel<<<NB * 2, 1024, SMEM2>>>(U1, U2, U3, out);
}

// round 9
// speedup vs baseline: 1.1688x; 1.1688x over previous
#include <cuda_runtime.h>
#include <math.h>
#include <cstdint>

typedef unsigned long long ull;

// Problem constants
#define L_STEPS 128
#define NB 64
#define HID 4096            // 32*16*8
#define T1S 128             // t1 row stride (words)
#define T2R 160             // t2 row stride; (e,c) -> e*10 + c
#define L_PER 16            // timesteps per xw CTA

// XW scratch: (L, 3, N, 4096) fp32 = 402 MB.
__device__ float g_xw[(size_t)L_STEPS * 3 * NB * HID];

__device__ __forceinline__ void fma2(ull& acc, ull a, ull b) {
    asm("fma.rn.f32x2 %0, %1, %2, %0;" : "+l"(acc) : "l"(a), "l"(b));
}
__device__ __forceinline__ ull dup2(float x) {
    ull r; asm("mov.b64 %0, {%1, %1};" : "=l"(r) : "f"(x)); return r;
}
__device__ __forceinline__ ull pack2(float lo, float hi) {
    ull r; asm("mov.b64 %0, {%1, %2};" : "=l"(r) : "f"(lo), "f"(hi)); return r;
}
__device__ __forceinline__ uint32_t smem_u32(const void* p) {
    uint32_t a;
    asm("{ .reg .u64 t; cvta.to.shared.u64 t, %1; cvt.u32.u64 %0, t; }" : "=r"(a) : "l"(p));
    return a;
}
__device__ __forceinline__ uint32_t mapa_u32(uint32_t addr, uint32_t rank) {
    uint32_t r;
    asm("mapa.shared::cluster.u32 %0, %1, %2;" : "=r"(r) : "r"(addr), "r"(rank));
    return r;
}
__device__ __forceinline__ void st_cluster_b64(uint32_t addr, ull v) {
    asm volatile("st.shared::cluster.b64 [%0], %1;" :: "r"(addr), "l"(v) : "memory");
}

// ---------------------------------------------------------------------------
// Stage 1: XW[l,g,n,:] for 16 timesteps per CTA. Grid (NB, L/16), 512 threads.
// Weights loaded once; x double-buffered (LDG for l+1 hidden under p1/p2).
// Per l: fused p1+p2 per warp (12 warps x 8 rows, syncwarp), sync, p3, sync.
// ---------------------------------------------------------------------------
__global__ __launch_bounds__(512) void xw_kernel(
    const float* __restrict__ x,
    const float* __restrict__ W1,   // (3,32,32)
    const float* __restrict__ W2,   // (3,16,16)
    const float* __restrict__ W3)   // (3,8,8)
{
    extern __shared__ float sm[];
    float* xs  = sm;              // 2 x 4096 (double buffer): x[a][b*8+c]
    float* t1  = xs + 8192;       // 96*T1S = 12288, rows r = g*32+d
    float* t2  = t1 + 12288;      // 96*T2R = 15360
    float* w1t = t2 + 15360;      // 3072: w1t[a*96 + g*32 + d] = W1[g,d,a]
    float* w2t = w1t + 3072;      // 768:  w2t[g*256 + b*16 + e] = W2[g,e,b]
    float* w3s = w2t + 768;       // 192

    const int t  = threadIdx.x;
    const int n  = blockIdx.x;
    const int l0 = blockIdx.y * L_PER;

    for (int i = t; i < 3072; i += 512) {
        int g = i >> 10, rem = i & 1023, d = rem >> 5, a = rem & 31;
        w1t[a * 96 + g * 32 + d] = W1[i];
    }
    for (int i = t; i < 768; i += 512) {
        int g = i >> 8, rem = i & 255, e = rem >> 4, b = rem & 15;
        w2t[g * 256 + b * 16 + e] = W2[i];
    }
    for (int i = t; i < 192; i += 512) w3s[i] = W3[i];
    // initial x load into buffer 0
    {
        const float4* xg4 = reinterpret_cast<const float4*>(x + ((size_t)n * L_STEPS + l0) * HID);
        float4* xs4 = reinterpret_cast<float4*>(xs);
        xs4[t] = xg4[t];
        xs4[t + 512] = xg4[t + 512];
    }
    __syncthreads();

    const int warp = t >> 5, lane = t & 31;
    const int r0  = warp * 8;           // 8 rows per warp (warps 0..11)
    const int bc0 = lane * 4;           // 4 cols per lane (p1)
    const int e2  = lane >> 1;          // p2: e
    const int c4  = (lane & 1) * 4;     // p2: c-half

    for (int ll = 0; ll < L_PER; ll++) {
        const int l = l0 + ll;
        float* cur = xs + (ll & 1) * 4096;
        float* nxt = xs + ((ll & 1) ^ 1) * 4096;

        // prefetch next l's x into registers (hidden under p1/p2)
        float4 pf0, pf1;
        if (ll + 1 < L_PER) {
            const float4* xg4 = reinterpret_cast<const float4*>(
                x + ((size_t)n * L_STEPS + l + 1) * HID);
            pf0 = xg4[t];
            pf1 = xg4[t + 512];
        }

        if (warp < 12) {
            // ---- fused p1: t1[r][bc] = sum_a W1t[a][r] * x[a][bc] ----
            ull acc[8][2];
#pragma unroll
            for (int j = 0; j < 8; j++) { acc[j][0] = 0; acc[j][1] = 0; }
#pragma unroll
            for (int a = 0; a < 32; a++) {
                ulonglong2 xv = *reinterpret_cast<const ulonglong2*>(&cur[a * 128 + bc0]);
                float4 wa = *reinterpret_cast<const float4*>(&w1t[a * 96 + r0]);
                float4 wb = *reinterpret_cast<const float4*>(&w1t[a * 96 + r0 + 4]);
                ull w0 = dup2(wa.x), w1 = dup2(wa.y), w2 = dup2(wa.z), w3 = dup2(wa.w);
                ull w4 = dup2(wb.x), w5 = dup2(wb.y), w6 = dup2(wb.z), w7 = dup2(wb.w);
                fma2(acc[0][0], w0, xv.x);  fma2(acc[0][1], w0, xv.y);
                fma2(acc[1][0], w1, xv.x);  fma2(acc[1][1], w1, xv.y);
                fma2(acc[2][0], w2, xv.x);  fma2(acc[2][1], w2, xv.y);
                fma2(acc[3][0], w3, xv.x);  fma2(acc[3][1], w3, xv.y);
                fma2(acc[4][0], w4, xv.x);  fma2(acc[4][1], w4, xv.y);
                fma2(acc[5][0], w5, xv.x);  fma2(acc[5][1], w5, xv.y);
                fma2(acc[6][0], w6, xv.x);  fma2(acc[6][1], w6, xv.y);
                fma2(acc[7][0], w7, xv.x);  fma2(acc[7][1], w7, xv.y);
            }
#pragma unroll
            for (int j = 0; j < 8; j++) {
                ulonglong2 st; st.x = acc[j][0]; st.y = acc[j][1];
                *reinterpret_cast<ulonglong2*>(&t1[(r0 + j) * T1S + bc0]) = st;
            }
            __syncwarp();

            // ---- fused p2: t2[r][e*10+c] = sum_b W2[g,e,b]*t1[r][b*8+c] ----
            const int g = warp >> 2;
            const float* w2g = w2t + g * 256;
            ull a2[8][2];
#pragma unroll
            for (int j = 0; j < 8; j++) { a2[j][0] = 0; a2[j][1] = 0; }
#pragma unroll
            for (int b = 0; b < 16; b++) {
                ull wd = dup2(w2g[b * 16 + e2]);
#pragma unroll
                for (int j = 0; j < 8; j++) {
                    ulonglong2 tv = *reinterpret_cast<const ulonglong2*>(
                        &t1[(r0 + j) * T1S + b * 8 + c4]);
                    fma2(a2[j][0], wd, tv.x);
                    fma2(a2[j][1], wd, tv.y);
                }
            }
#pragma unroll
            for (int j = 0; j < 8; j++) {
                float* t2r = t2 + (r0 + j) * T2R + e2 * 10 + c4;
                *reinterpret_cast<ull*>(t2r)     = a2[j][0];
                *reinterpret_cast<ull*>(t2r + 2) = a2[j][1];
            }
        }
        __syncthreads();

        // ---- p3: out[(d*16+e)*8+f] = sum_c W3[g,f,c] * t2[g*32+d][e*10+c] ----
        {
            const int d = t >> 4, e = t & 15;
#pragma unroll
            for (int g = 0; g < 3; g++) {
                const float* t2c = t2 + (g * 32 + d) * T2R + e * 10;
                float col[8];
#pragma unroll
                for (int k = 0; k < 4; k++) {
                    float2 v = *reinterpret_cast<const float2*>(&t2c[k * 2]);
                    col[2 * k] = v.x;  col[2 * k + 1] = v.y;
                }
                const float* w3g = w3s + g * 64;
                float o[8];
#pragma unroll
                for (int f = 0; f < 8; f++) {
                    float4 ua = *reinterpret_cast<const float4*>(&w3g[f * 8]);
                    float4 ub = *reinterpret_cast<const float4*>(&w3g[f * 8 + 4]);
                    o[f] = ua.x * col[0] + ua.y * col[1] + ua.z * col[2] + ua.w * col[3]
                         + ub.x * col[4] + ub.y * col[5] + ub.z * col[6] + ub.w * col[7];
                }
                float* outg = g_xw + (((size_t)l * 3 + g) * NB + n) * HID + t * 8;
                *reinterpret_cast<float4*>(outg)     = make_float4(o[0], o[1], o[2], o[3]);
                *reinterpret_cast<float4*>(outg + 4) = make_float4(o[4], o[5], o[6], o[7]);
            }
        }

        // store prefetched x into the other buffer
        if (ll + 1 < L_PER) {
            float4* nx4 = reinterpret_cast<float4*>(nxt);
            nx4[t] = pf0;
            nx4[t + 512] = pf1;
        }
        __syncthreads();   // t1/t2 reuse + x buffer visibility
    }
}

// ---------------------------------------------------------------------------
// Stage 2: GRU recurrence. Cluster of 2 CTAs per sample (128 CTAs, 512 thr).
// CTA owns d in [rank*16, rank*16+16). Warps 0-11: fused p1+p2 (syncwarp);
// warps 12-15: store out[l-1] from hc (race-free). One syncthreads, p3,
// DSMEM half-exchange, one cluster barrier per step.
// ---------------------------------------------------------------------------
__global__ __launch_bounds__(512) __cluster_dims__(2, 1, 1)
void gru_kernel(
    const float* __restrict__ U1,   // (3,32,32)
    const float* __restrict__ U2,   // (3,16,16)
    const float* __restrict__ U3,   // (3,8,8)
    float* __restrict__ out)        // outs (N,L,4096) then h_last (N,4096)
{
    extern __shared__ float sm[];
    float* h0  = sm;                 // 4096
    float* h1  = h0 + 4096;          // 4096
    float* t1  = h1 + 4096;          // 48*T1S = 6144   rows r = g*16+dd
    float* t2  = t1 + 6144;          // 48*T2R = 7680
    float* u1t = t2 + 7680;          // 1536: u1t[a*48 + g*16 + dd] = U1[g, rank*16+dd, a]
    float* w2t = u1t + 1536;         // 768:  w2t[g*256 + b*16 + e] = U2[g,e,b]
    float* u3s = w2t + 768;          // 192

    const int t    = threadIdx.x;
    const int n    = blockIdx.x >> 1;
    const int rank = blockIdx.x & 1;
    const int peer = rank ^ 1;

    for (int i = t; i < 4096; i += 512) h0[i] = 0.f;
    for (int i = t; i < 1536; i += 512) {
        int g = i >> 9, rem = i & 511, dd = rem >> 5, a = rem & 31;
        u1t[a * 48 + g * 16 + dd] = U1[((g * 32) + rank * 16 + dd) * 32 + a];
    }
    for (int i = t; i < 768; i += 512) {
        int g = i >> 8, rem = i & 255, e = rem >> 4, b = rem & 15;
        w2t[g * 256 + b * 16 + e] = U2[i];
    }
    for (int i = t; i < 192; i += 512) u3s[i] = U3[i];
    __syncthreads();

    const uint32_t h0a = smem_u32(h0);
    const uint32_t h1a = smem_u32(h1);

    const int warp = t >> 5, lane = t & 31;
    // fused p1+p2 (warps 0..11): r0 = 4 rows; lane -> 4 cols (p1) / (e,c-half) (p2)
    const int r0  = warp * 4;
    const int bc0 = lane * 4;
    const int e2  = lane >> 1;
    const int c4  = (lane & 1) * 4;
    // p3: warp = dd; lane -> (e3, f0..f0+3)
    const int e3 = lane >> 1;
    const int f0 = (lane & 1) * 4;
    const int gbase = ((rank * 16 + warp) * 16 + e3) * 8 + f0;  // 4 global hidden elems

    float* hc = h0;
    float* hn = h1;

    for (int l = 0; l < L_STEPS; l++) {
        // XW prefetch for phase 3 — issued first, hidden under fused p1+p2
        float4 xf[3];
#pragma unroll
        for (int g = 0; g < 3; g++)
            xf[g] = *reinterpret_cast<const float4*>(
                g_xw + (((size_t)l * 3 + g) * NB + n) * HID + gbase);

        if (warp < 12) {
            // ---- fused p1: t1[r][bc] = sum_a u1t[a][r]*hc[a*128+bc] ----
            ull acc2[4][2];
#pragma unroll
            for (int j = 0; j < 4; j++) { acc2[j][0] = 0; acc2[j][1] = 0; }
#pragma unroll
            for (int a = 0; a < 32; a++) {
                ulonglong2 hv = *reinterpret_cast<const ulonglong2*>(&hc[a * 128 + bc0]);
                float4 wv = *reinterpret_cast<const float4*>(&u1t[a * 48 + r0]);
                ull w0 = dup2(wv.x), w1 = dup2(wv.y), w2 = dup2(wv.z), w3 = dup2(wv.w);
                fma2(acc2[0][0], w0, hv.x);  fma2(acc2[0][1], w0, hv.y);
                fma2(acc2[1][0], w1, hv.x);  fma2(acc2[1][1], w1, hv.y);
                fma2(acc2[2][0], w2, hv.x);  fma2(acc2[2][1], w2, hv.y);
                fma2(acc2[3][0], w3, hv.x);  fma2(acc2[3][1], w3, hv.y);
            }
#pragma unroll
            for (int j = 0; j < 4; j++) {
                ulonglong2 st; st.x = acc2[j][0]; st.y = acc2[j][1];
                *reinterpret_cast<ulonglong2*>(&t1[(r0 + j) * T1S + bc0]) = st;
            }
            __syncwarp();

            // ---- fused p2: t2[r][e*10+c] = sum_b U2[g,e,b]*t1[r][b*8+c] ----
            const int g = warp >> 2;
            const float* w2g = w2t + g * 256;
            ull a2[4][2];
#pragma unroll
            for (int j = 0; j < 4; j++) { a2[j][0] = 0; a2[j][1] = 0; }
#pragma unroll
            for (int b = 0; b < 16; b++) {
                ull wd = dup2(w2g[b * 16 + e2]);
#pragma unroll
                for (int j = 0; j < 4; j++) {
                    ulonglong2 tv = *reinterpret_cast<const ulonglong2*>(
                        &t1[(r0 + j) * T1S + b * 8 + c4]);
                    fma2(a2[j][0], wd, tv.x);
                    fma2(a2[j][1], wd, tv.y);
                }
            }
#pragma unroll
            for (int j = 0; j < 4; j++) {
                float* t2r = t2 + (r0 + j) * T2R + e2 * 10 + c4;
                *reinterpret_cast<ull*>(t2r)     = a2[j][0];
                *reinterpret_cast<ull*>(t2r + 2) = a2[j][1];
            }
        } else if (l > 0) {
            // ---- warps 12-15: store out[l-1] from hc (hc is read-only in p1) ----
            const int tt = t - 384;          // 0..127
            float* outp = out + ((size_t)n * L_STEPS + (l - 1)) * HID;
#pragma unroll
            for (int j = 0; j < 8; j++) {
                int i = (tt * 8 + j * 128 * 8) % 4096;   // coalesced: tt + j*128 quads
                // simpler: quad index q = j*128 + tt
                int q = j * 128 + tt;
                float4 v = *reinterpret_cast<const float4*>(&hc[q * 4]);
                *reinterpret_cast<float4*>(&outp[q * 4]) = v;
                (void)i;
            }
        }
        __syncthreads();

        // ---- p3: mode-3 + gate combine for 4 elements (gbase..+3) ----
        float hu[3][4];
#pragma unroll
        for (int g = 0; g < 3; g++) {
            const float* t2c = t2 + (g * 16 + warp) * T2R + e3 * 10;
            float col[8];
#pragma unroll
            for (int k = 0; k < 4; k++) {
                float2 v = *reinterpret_cast<const float2*>(&t2c[k * 2]);
                col[2 * k] = v.x;  col[2 * k + 1] = v.y;
            }
            const float* u3g = u3s + g * 64;
#pragma unroll
            for (int j = 0; j < 4; j++) {
                float4 ua = *reinterpret_cast<const float4*>(&u3g[(f0 + j) * 8]);
                float4 ub = *reinterpret_cast<const float4*>(&u3g[(f0 + j) * 8 + 4]);
                hu[g][j] = ua.x * col[0] + ua.y * col[1] + ua.z * col[2] + ua.w * col[3]
                         + ub.x * col[4] + ub.y * col[5] + ub.z * col[6] + ub.w * col[7];
            }
        }
        float4 ho = *reinterpret_cast<const float4*>(&hc[gbase]);
        float hold[4] = {ho.x, ho.y, ho.z, ho.w};
        float xz[4] = {xf[0].x, xf[0].y, xf[0].z, xf[0].w};
        float xr[4] = {xf[1].x, xf[1].y, xf[1].z, xf[1].w};
        float xh[4] = {xf[2].x, xf[2].y, xf[2].z, xf[2].w};

        float res[4];
#pragma unroll
        for (int j = 0; j < 4; j++) {
            float z  = 1.f / (1.f + __expf(-(xz[j] + hu[0][j])));
            float r  = 1.f / (1.f + __expf(-(xr[j] + hu[1][j])));
            float ax = xh[j] + r * hu[2][j];
            float e2x = __expf(2.f * ax);
            float hh = 1.f - 2.f / (e2x + 1.f);      // tanh, NaN-safe
            res[j] = z * hold[j] + (1.f - z) * hh;
        }
        *reinterpret_cast<float4*>(&hn[gbase]) = make_float4(res[0], res[1], res[2], res[3]);

        // publish our half to peer's hn via DSMEM (2x b64)
        {
            uint32_t hna = (l & 1) ? h0a : h1a;
            uint32_t ra = mapa_u32(hna + (uint32_t)gbase * 4u, (uint32_t)peer);
            st_cluster_b64(ra,     pack2(res[0], res[1]));
            st_cluster_b64(ra + 8, pack2(res[2], res[3]));
        }

        asm volatile("barrier.cluster.arrive.aligned;" ::: "memory");
        asm volatile("barrier.cluster.wait.aligned;"   ::: "memory");

        float* tmp = hc; hc = hn; hn = tmp;
    }

    // out[L-1] (hc now holds h(L-1)) + h_last
    {
        float* outp = out + ((size_t)n * L_STEPS + (L_STEPS - 1)) * HID;
        for (int q = t; q < 1024; q += 512) {
            float4 v = *reinterpret_cast<const float4*>(&hc[q * 4]);
            *reinterpret_cast<float4*>(&outp[q * 4]) = v;
        }
        float* hl = out + (size_t)NB * L_STEPS * HID + (size_t)n * HID + rank * 2048;
        const float* hsrc = hc + rank * 2048;
        for (int i = t; i < 2048; i += 512) hl[i] = hsrc[i];
    }
}

// ---------------------------------------------------------------------------
extern "C" void kernel_launch(void* const* d_in, const int* in_sizes, int n_in,
                              void* d_out, int out_size)
{
    const float* x  = (const float*)d_in[0];
    const float* W1 = (const float*)d_in[1];
    const float* W2 = (const float*)d_in[2];
    const float* W3 = (const float*)d_in[3];
    const float* U1 = (const float*)d_in[4];
    const float* U2 = (const float*)d_in[5];
    const float* U3 = (const float*)d_in[6];
    float* out = (float*)d_out;

    const int SMEM1 = (8192 + 12288 + 15360 + 3072 + 768 + 192) * (int)sizeof(float);
    const int SMEM2 = (4096 * 2 + 6144 + 7680 + 1536 + 768 + 192) * (int)sizeof(float);

    cudaFuncSetAttribute(xw_kernel,  cudaFuncAttributeMaxDynamicSharedMemorySize, SMEM1);
    cudaFuncSetAttribute(gru_kernel, cudaFuncAttributeMaxDynamicSharedMemorySize, SMEM2);

    dim3 grid1(NB, L_STEPS / L_PER);
    xw_kernel<<<grid1, 512, SMEM1>>>(x, W1, W2, W3);
    gru_kernel<<<NB * 2, 512, SMEM2>>>(U1, U2, U3, out);
}